// round 3
// baseline (speedup 1.0000x reference)
#include <cuda_runtime.h>
#include <math.h>

#define BB 4
#define TT 1024
#define EE 512
#define HH 8
#define DHH 64
#define KVL 2304
#define MEML 1024
#define CMEML 256
#define SCL 0.125f
#define PAD 68

#define OFF_LOGITS  0LL
#define OFF_NEWMEM  2097152LL
#define OFF_NEWCMEM 4194304LL
#define OFF_AUX     4718592LL
#define OFF_W       4718593LL

// scratch arena offsets (floats)
#define S_Q     0LL
#define S_KVIN  2097152LL
#define S_KV    6815744LL
#define S_CM    16252928LL
#define S_CKV   16777216LL
#define S_CONVA 17825792LL
#define S_O     19922944LL
#define S_M     22020096LL
#define S_L     22052864LL
#define S_AUXP  22085632LL
#define S_TOTAL 22086144LL

__device__ float g_scratch[S_TOTAL];

__global__ void k_concat(const float* __restrict__ x, const float* __restrict__ mem,
                         const float* __restrict__ cmem, float* __restrict__ kvin){
    long long i = (long long)blockIdx.x*blockDim.x + threadIdx.x;
    const long long n4 = (long long)BB*KVL*EE/4;
    if(i >= n4) return;
    long long idx = i*4;
    int b = (int)(idx / ((long long)KVL*EE));
    int rem = (int)(idx % ((long long)KVL*EE));
    int j = rem / EE, e = rem % EE;
    const float* src;
    if(j < CMEML)            src = cmem + ((long long)b*CMEML + j)*EE + e;
    else if(j < CMEML+MEML)  src = mem  + ((long long)b*MEML + (j-CMEML))*EE + e;
    else                     src = x    + ((long long)b*TT   + (j-CMEML-MEML))*EE + e;
    ((float4*)kvin)[i] = *(const float4*)src;
}

__global__ void k_convA(const float* __restrict__ mem, float* __restrict__ convA){
    int i = blockIdx.x*blockDim.x + threadIdx.x;
    if(i >= BB*CMEML*EE*4) return;
    int b = i >> 19;
    int rem = i & ((1<<19)-1);
    int r = rem >> 11;
    int t2 = rem & 2047;
    int e = t2 >> 2, kk = t2 & 3;
    convA[i] = mem[((long long)b*MEML + r*4 + kk)*EE + e];
}

// C[M,N] = A[M,K] @ B (+bias). BT=0: B is KxN row-major; BT=1: B is NxK row-major.
template<int BT>
__global__ void __launch_bounds__(256) k_gemm(const float* __restrict__ A,
                                              const float* __restrict__ Bm,
                                              const float* __restrict__ bias,
                                              float* __restrict__ C,
                                              int M, int N, int K){
    __shared__ float As[16][132];
    __shared__ float Bs[16][68];
    const int tid = threadIdx.x;
    const int ty = tid >> 4, tx = tid & 15;
    const int m0 = blockIdx.y * 128;
    const int n0 = blockIdx.x * 64;
    float acc[8][4];
    #pragma unroll
    for(int r=0;r<8;r++)
        #pragma unroll
        for(int c=0;c<4;c++) acc[r][c] = 0.f;

    for(int k0=0; k0<K; k0+=16){
        #pragma unroll
        for(int l=0;l<8;l++){
            int idx = tid + l*256;
            int row = idx >> 4, col = idx & 15;
            As[col][row] = A[(long long)(m0+row)*K + k0 + col];
        }
        #pragma unroll
        for(int l=0;l<4;l++){
            int idx = tid + l*256;
            if(BT){
                int col = idx >> 4, kk = idx & 15;
                Bs[kk][col] = Bm[(long long)(n0+col)*K + k0 + kk];
            } else {
                int kk = idx >> 6, col = idx & 63;
                Bs[kk][col] = Bm[(long long)(k0+kk)*N + n0 + col];
            }
        }
        __syncthreads();
        #pragma unroll
        for(int kk=0;kk<16;kk++){
            float a[8], bb[4];
            #pragma unroll
            for(int r=0;r<8;r++) a[r] = As[kk][ty*8+r];
            #pragma unroll
            for(int c=0;c<4;c++) bb[c] = Bs[kk][tx*4+c];
            #pragma unroll
            for(int r=0;r<8;r++)
                #pragma unroll
                for(int c=0;c<4;c++)
                    acc[r][c] += a[r]*bb[c];
        }
        __syncthreads();
    }
    #pragma unroll
    for(int r=0;r<8;r++){
        int mrow = m0 + ty*8 + r;
        #pragma unroll
        for(int c=0;c<4;c++){
            int n = n0 + tx*4 + c;
            float v = acc[r][c];
            if(bias) v += bias[n];
            C[(long long)mrow*N + n] = v;
        }
    }
}

__global__ void __launch_bounds__(256) k_attn(const float* __restrict__ pe,
                                              float* __restrict__ w,
                                              const float* __restrict__ gq,
                                              const float* __restrict__ gkv,
                                              float* __restrict__ go,
                                              float* __restrict__ gm,
                                              float* __restrict__ gl){
    extern __shared__ float sm[];
    float* q_s   = sm;
    float* k_s   = q_s + 64*PAD;
    float* v_s   = k_s + 64*PAD;
    float* p_s   = v_s + 64*PAD;
    float* pos_s = p_s + 64*PAD;

    const int it = blockIdx.x, h = blockIdx.y, b = blockIdx.z;
    const int i0 = it*64;
    const int t  = threadIdx.x;
    const int ti = t >> 4;
    const int tj = t & 15;

    {
        const float4* qsrc = (const float4*)(gq + ((long long)(b*TT + i0))*EE + h*DHH);
        for(int idx=t; idx<64*16; idx+=256){
            int row = idx>>4, c4 = idx&15;
            ((float4*)q_s)[row*17 + c4] = qsrc[(long long)row*128 + c4];
        }
    }

    float m[4], l[4], acc[4][4];
    #pragma unroll
    for(int a=0;a<4;a++){
        m[a] = -INFINITY; l[a] = 0.f;
        #pragma unroll
        for(int c=0;c<4;c++) acc[a][c] = 0.f;
    }

    const long long wbase = (((long long)(b*HH + h))*TT + i0)*KVL;
    const float* kbase  = gkv + ((long long)b*KVL)*(2*EE) + h*DHH;
    const float* vbase  = kbase + EE;
    const float* pebase = pe + (long long)h*KVL*DHH;

    for(int ch=0; ch<KVL/64; ch++){
        const int j0 = ch*64;
        const int rb = 960 + j0 - i0;
        __syncthreads();
        for(int idx=t; idx<64*16; idx+=256){
            int row = idx>>4, c4 = idx&15;
            ((float4*)k_s)[row*17+c4] = ((const float4*)(kbase + (long long)(j0+row)*(2*EE)))[c4];
            ((float4*)v_s)[row*17+c4] = ((const float4*)(vbase + (long long)(j0+row)*(2*EE)))[c4];
        }
        for(int idx=t; idx<128*16; idx+=256){
            int row = idx>>4, c4 = idx&15;
            float4 pv = make_float4(0.f,0.f,0.f,0.f);
            if(rb + row < KVL) pv = ((const float4*)(pebase + (long long)(rb+row)*DHH))[c4];
            ((float4*)pos_s)[row*17+c4] = pv;
        }
        __syncthreads();

        float s[4][4];
        #pragma unroll
        for(int a=0;a<4;a++)
            #pragma unroll
            for(int c=0;c<4;c++) s[a][c] = 0.f;
        const int rb2 = 63 + tj - ti;
        {
            const float4* q4 = (const float4*)q_s;
            const float4* k4 = (const float4*)k_s;
            const float4* p4 = (const float4*)pos_s;
            #pragma unroll
            for(int d=0; d<16; d++){
                float4 qv[4], kv[4], pv[7];
                #pragma unroll
                for(int a=0;a<4;a++) qv[a] = q4[(ti + 16*a)*17 + d];
                #pragma unroll
                for(int c=0;c<4;c++) kv[c] = k4[(tj + 16*c)*17 + d];
                #pragma unroll
                for(int u=0;u<7;u++) pv[u] = p4[(rb2 + 16*(u-3))*17 + d];
                #pragma unroll
                for(int a=0;a<4;a++){
                    #pragma unroll
                    for(int c=0;c<4;c++){
                        float4 kp = pv[3 + c - a];
                        s[a][c] += qv[a].x*(kv[c].x + kp.x)
                                 + qv[a].y*(kv[c].y + kp.y)
                                 + qv[a].z*(kv[c].z + kp.z)
                                 + qv[a].w*(kv[c].w + kp.w);
                    }
                }
            }
        }
        #pragma unroll
        for(int a=0;a<4;a++)
            #pragma unroll
            for(int c=0;c<4;c++){
                s[a][c] *= SCL;
                p_s[(ti+16*a)*PAD + tj + 16*c] = s[a][c];
            }
        __syncthreads();
        for(int idx=t; idx<64*64; idx+=256){
            int row = idx>>6, col = idx&63;
            w[wbase + (long long)row*KVL + j0 + col] = p_s[row*PAD + col];
        }
        __syncthreads();
        #pragma unroll
        for(int a=0;a<4;a++){
            float mc = fmaxf(fmaxf(s[a][0], s[a][1]), fmaxf(s[a][2], s[a][3]));
            mc = fmaxf(mc, __shfl_xor_sync(0xffffffffu, mc, 1));
            mc = fmaxf(mc, __shfl_xor_sync(0xffffffffu, mc, 2));
            mc = fmaxf(mc, __shfl_xor_sync(0xffffffffu, mc, 4));
            mc = fmaxf(mc, __shfl_xor_sync(0xffffffffu, mc, 8));
            float mn = fmaxf(m[a], mc);
            float corr = __expf(m[a] - mn);
            float ps = 0.f;
            #pragma unroll
            for(int c=0;c<4;c++){
                float p = __expf(s[a][c] - mn);
                ps += p;
                p_s[(ti+16*a)*PAD + tj + 16*c] = p;
            }
            ps += __shfl_xor_sync(0xffffffffu, ps, 1);
            ps += __shfl_xor_sync(0xffffffffu, ps, 2);
            ps += __shfl_xor_sync(0xffffffffu, ps, 4);
            ps += __shfl_xor_sync(0xffffffffu, ps, 8);
            l[a] = l[a]*corr + ps;
            m[a] = mn;
            #pragma unroll
            for(int c=0;c<4;c++) acc[a][c] *= corr;
        }
        __syncthreads();
        {
            const float4* v4 = (const float4*)v_s;
            #pragma unroll 4
            for(int j=0;j<64;j++){
                float4 vv = v4[j*17 + tj];
                #pragma unroll
                for(int a=0;a<4;a++){
                    float pj = p_s[(ti+16*a)*PAD + j];
                    acc[a][0] += pj*vv.x;
                    acc[a][1] += pj*vv.y;
                    acc[a][2] += pj*vv.z;
                    acc[a][3] += pj*vv.w;
                }
            }
        }
    }
    #pragma unroll
    for(int a=0;a<4;a++){
        float inv = 1.f/l[a];
        float4 o4 = make_float4(acc[a][0]*inv, acc[a][1]*inv, acc[a][2]*inv, acc[a][3]*inv);
        ((float4*)(go + ((long long)(b*TT + i0 + ti + 16*a))*EE + h*DHH))[tj] = o4;
        if(tj == 0){
            long long gmi = ((long long)(b*HH + h))*TT + i0 + ti + 16*a;
            gm[gmi] = m[a]; gl[gmi] = l[a];
        }
    }
}

__global__ void k_rescale(float* __restrict__ w, const float* __restrict__ gm,
                          const float* __restrict__ gl){
    long long row = blockIdx.x;
    float mm = gm[row];
    float invl = 1.f / gl[row];
    float* wr = w + row*KVL;
    for(int j=threadIdx.x; j<KVL; j+=blockDim.x)
        wr[j] = __expf(wr[j] - mm) * invl;
}

__global__ void __launch_bounds__(256) k_aux(const float* __restrict__ gq,
                                             const float* __restrict__ gkv,
                                             const float* __restrict__ gckv,
                                             float* __restrict__ auxp){
    extern __shared__ float sm[];
    float* q_s  = sm;
    float* k_s  = q_s + 64*PAD;
    float* v_s  = k_s + 64*PAD;
    float* p_s  = v_s + 64*PAD;
    float* o1_s = p_s + 64*PAD;
    __shared__ float red[256];

    const int it = blockIdx.x, h = blockIdx.y, b = blockIdx.z;
    const int i0 = it*64;
    const int t  = threadIdx.x;
    const int ti = t >> 4, tj = t & 15;

    {
        const float4* qsrc = (const float4*)(gq + ((long long)(b*TT + i0))*EE + h*DHH);
        for(int idx=t; idx<64*16; idx+=256){
            int row = idx>>4, c4 = idx&15;
            ((float4*)q_s)[row*17+c4] = qsrc[(long long)row*128 + c4];
        }
    }

    float dsum = 0.f;
    for(int pass=0; pass<2; pass++){
        const int nch = pass ? (CMEML/64) : (MEML/64);
        const float* kb = pass ? (gckv + ((long long)b*CMEML)*(2*EE) + h*DHH)
                               : (gkv  + ((long long)(b*KVL + CMEML))*(2*EE) + h*DHH);
        float m[4], l[4], acc[4][4];
        #pragma unroll
        for(int a=0;a<4;a++){
            m[a] = -INFINITY; l[a] = 0.f;
            #pragma unroll
            for(int c=0;c<4;c++) acc[a][c] = 0.f;
        }
        for(int ch=0; ch<nch; ch++){
            const int j0 = ch*64;
            __syncthreads();
            for(int idx=t; idx<64*16; idx+=256){
                int row = idx>>4, c4 = idx&15;
                ((float4*)k_s)[row*17+c4] = ((const float4*)(kb      + (long long)(j0+row)*(2*EE)))[c4];
                ((float4*)v_s)[row*17+c4] = ((const float4*)(kb + EE + (long long)(j0+row)*(2*EE)))[c4];
            }
            __syncthreads();
            float s[4][4];
            #pragma unroll
            for(int a=0;a<4;a++)
                #pragma unroll
                for(int c=0;c<4;c++) s[a][c] = 0.f;
            {
                const float4* q4 = (const float4*)q_s;
                const float4* k4 = (const float4*)k_s;
                #pragma unroll
                for(int d=0; d<16; d++){
                    float4 qv[4], kv[4];
                    #pragma unroll
                    for(int a=0;a<4;a++) qv[a] = q4[(ti + 16*a)*17 + d];
                    #pragma unroll
                    for(int c=0;c<4;c++) kv[c] = k4[(tj + 16*c)*17 + d];
                    #pragma unroll
                    for(int a=0;a<4;a++)
                        #pragma unroll
                        for(int c=0;c<4;c++)
                            s[a][c] += qv[a].x*kv[c].x + qv[a].y*kv[c].y
                                     + qv[a].z*kv[c].z + qv[a].w*kv[c].w;
                }
            }
            #pragma unroll
            for(int a=0;a<4;a++){
                #pragma unroll
                for(int c=0;c<4;c++) s[a][c] *= SCL;
                float mc = fmaxf(fmaxf(s[a][0], s[a][1]), fmaxf(s[a][2], s[a][3]));
                mc = fmaxf(mc, __shfl_xor_sync(0xffffffffu, mc, 1));
                mc = fmaxf(mc, __shfl_xor_sync(0xffffffffu, mc, 2));
                mc = fmaxf(mc, __shfl_xor_sync(0xffffffffu, mc, 4));
                mc = fmaxf(mc, __shfl_xor_sync(0xffffffffu, mc, 8));
                float mn = fmaxf(m[a], mc);
                float corr = __expf(m[a] - mn);
                float ps = 0.f;
                #pragma unroll
                for(int c=0;c<4;c++){
                    float p = __expf(s[a][c] - mn);
                    ps += p;
                    p_s[(ti+16*a)*PAD + tj + 16*c] = p;
                }
                ps += __shfl_xor_sync(0xffffffffu, ps, 1);
                ps += __shfl_xor_sync(0xffffffffu, ps, 2);
                ps += __shfl_xor_sync(0xffffffffu, ps, 4);
                ps += __shfl_xor_sync(0xffffffffu, ps, 8);
                l[a] = l[a]*corr + ps;
                m[a] = mn;
                #pragma unroll
                for(int c=0;c<4;c++) acc[a][c] *= corr;
            }
            __syncthreads();
            {
                const float4* v4 = (const float4*)v_s;
                #pragma unroll 4
                for(int j=0;j<64;j++){
                    float4 vv = v4[j*17 + tj];
                    #pragma unroll
                    for(int a=0;a<4;a++){
                        float pj = p_s[(ti+16*a)*PAD + j];
                        acc[a][0] += pj*vv.x;
                        acc[a][1] += pj*vv.y;
                        acc[a][2] += pj*vv.z;
                        acc[a][3] += pj*vv.w;
                    }
                }
            }
        }
        if(pass == 0){
            #pragma unroll
            for(int a=0;a<4;a++){
                float inv = 1.f/l[a];
                #pragma unroll
                for(int c=0;c<4;c++)
                    o1_s[(ti+16*a)*PAD + tj*4 + c] = acc[a][c]*inv;
            }
        } else {
            #pragma unroll
            for(int a=0;a<4;a++){
                float inv = 1.f/l[a];
                #pragma unroll
                for(int c=0;c<4;c++){
                    float d = o1_s[(ti+16*a)*PAD + tj*4 + c] - acc[a][c]*inv;
                    dsum += d*d;
                }
            }
        }
    }
    red[t] = dsum;
    __syncthreads();
    for(int s2=128; s2>0; s2>>=1){
        if(t < s2) red[t] += red[t + s2];
        __syncthreads();
    }
    if(t == 0)
        auxp[(blockIdx.z*8 + blockIdx.y)*16 + blockIdx.x] = red[0];
}

__global__ void k_auxfin(const float* __restrict__ auxp, float* __restrict__ dst){
    __shared__ float red[512];
    int t = threadIdx.x;
    red[t] = auxp[t];
    __syncthreads();
    for(int s2=256; s2>0; s2>>=1){
        if(t < s2) red[t] += red[t + s2];
        __syncthreads();
    }
    if(t == 0) dst[0] = red[0] / 2097152.0f;
}

extern "C" void kernel_launch(void* const* d_in, const int* in_sizes, int n_in,
                              void* d_out, int out_size) {
    const float* x      = (const float*)d_in[0];
    const float* mem    = (const float*)d_in[1];
    const float* cmem   = (const float*)d_in[2];
    const float* pe     = (const float*)d_in[3];
    const float* Wq     = (const float*)d_in[4];
    const float* Wkv    = (const float*)d_in[5];
    const float* Wout   = (const float*)d_in[6];
    const float* bout   = (const float*)d_in[7];
    const float* conv_w = (const float*)d_in[8];
    const float* conv_b = (const float*)d_in[9];
    float* out = (float*)d_out;

    float* S = 0;
    cudaGetSymbolAddress((void**)&S, g_scratch);
    float* sq    = S + S_Q;
    float* skvin = S + S_KVIN;
    float* skv   = S + S_KV;
    float* scm   = S + S_CM;
    float* sckv  = S + S_CKV;
    float* sconvA= S + S_CONVA;
    float* so    = S + S_O;
    float* sm_   = S + S_M;
    float* sl_   = S + S_L;
    float* sauxp = S + S_AUXP;

    cudaFuncSetAttribute(k_attn, cudaFuncAttributeMaxDynamicSharedMemorySize, (4*64+128)*PAD*4);
    cudaFuncSetAttribute(k_aux,  cudaFuncAttributeMaxDynamicSharedMemorySize, 5*64*PAD*4);

    // new_mem = x
    cudaMemcpyAsync(out + OFF_NEWMEM, x, (size_t)BB*TT*EE*4, cudaMemcpyDeviceToDevice);

    // kv_input concat + kv GEMM
    k_concat<<<(BB*KVL*EE/4 + 255)/256, 256>>>(x, mem, cmem, skvin);
    k_gemm<0><<<dim3(2*EE/64, BB*KVL/128), 256>>>(skvin, Wkv, (const float*)0, skv, BB*KVL, 2*EE, EE);

    // q GEMM
    k_gemm<0><<<dim3(EE/64, BB*TT/128), 256>>>(x, Wq, (const float*)0, sq, BB*TT, EE, EE);

    // conv (compressed_mem) + new_cmem + ckv GEMM
    k_convA<<<(BB*CMEML*EE*4 + 255)/256, 256>>>(mem, sconvA);
    k_gemm<1><<<dim3(EE/64, BB*CMEML/128), 256>>>(sconvA, conv_w, conv_b, scm, BB*CMEML, EE, EE*4);
    cudaMemcpyAsync(out + OFF_NEWCMEM, scm, (size_t)BB*CMEML*EE*4, cudaMemcpyDeviceToDevice);
    k_gemm<0><<<dim3(2*EE/64, BB*CMEML/128), 256>>>(scm, Wkv, (const float*)0, sckv, BB*CMEML, 2*EE, EE);

    // attention
    k_attn<<<dim3(TT/64, HH, BB), 256, (4*64+128)*PAD*4>>>(pe, out + OFF_W, sq, skv, so, sm_, sl_);
    k_rescale<<<BB*HH*TT, 256>>>(out + OFF_W, sm_, sl_);

    // logits
    k_gemm<0><<<dim3(EE/64, BB*TT/128), 256>>>(so, Wout, bout, out + OFF_LOGITS, BB*TT, EE, EE);

    // aux loss
    k_aux<<<dim3(TT/64, HH, BB), 256, 5*64*PAD*4>>>(sq, skv, sckv, sauxp);
    k_auxfin<<<1, 512>>>(sauxp, out + OFF_AUX);
}

// round 4
// speedup vs baseline: 1.1740x; 1.1740x over previous
#include <cuda_runtime.h>
#include <math.h>
#include <stdint.h>

#define BB 4
#define TT 1024
#define EE 512
#define HH 8
#define DHH 64
#define KVL 2304
#define MEML 1024
#define CMEML 256
#define SCL 0.125f

#define OFF_LOGITS  0LL
#define OFF_NEWMEM  2097152LL
#define OFF_NEWCMEM 4194304LL
#define OFF_AUX     4718592LL
#define OFF_W       4718593LL

// scratch arena offsets (floats)
#define S_Q     0LL
#define S_KVIN  2097152LL
#define S_KV    6815744LL
#define S_CM    16252928LL
#define S_CKV   16777216LL
#define S_CONVA 17825792LL
#define S_O     19922944LL
#define S_M     22020096LL
#define S_L     22052864LL
#define S_AUXP  22085632LL
#define S_TOTAL 22086144LL

__device__ float g_scratch[S_TOTAL];

__device__ __forceinline__ float tf32r(float x){
    unsigned u;
    asm("cvt.rna.tf32.f32 %0, %1;" : "=r"(u) : "f"(x));
    return __uint_as_float(u);
}

__device__ __forceinline__ void mma_tf32(float d[4], const unsigned a[4], const unsigned b[2]){
    asm("mma.sync.aligned.m16n8k8.row.col.f32.tf32.tf32.f32 "
        "{%0,%1,%2,%3},{%4,%5,%6,%7},{%8,%9},{%0,%1,%2,%3};"
        : "+f"(d[0]),"+f"(d[1]),"+f"(d[2]),"+f"(d[3])
        : "r"(a[0]),"r"(a[1]),"r"(a[2]),"r"(a[3]), "r"(b[0]),"r"(b[1]));
}

__global__ void k_concat(const float* __restrict__ x, const float* __restrict__ mem,
                         const float* __restrict__ cmem, float* __restrict__ kvin){
    long long i = (long long)blockIdx.x*blockDim.x + threadIdx.x;
    const long long n4 = (long long)BB*KVL*EE/4;
    if(i >= n4) return;
    long long idx = i*4;
    int b = (int)(idx / ((long long)KVL*EE));
    int rem = (int)(idx % ((long long)KVL*EE));
    int j = rem / EE, e = rem % EE;
    const float* src;
    if(j < CMEML)            src = cmem + ((long long)b*CMEML + j)*EE + e;
    else if(j < CMEML+MEML)  src = mem  + ((long long)b*MEML + (j-CMEML))*EE + e;
    else                     src = x    + ((long long)b*TT   + (j-CMEML-MEML))*EE + e;
    ((float4*)kvin)[i] = *(const float4*)src;
}

__global__ void k_convA(const float* __restrict__ mem, float* __restrict__ convA){
    int i = blockIdx.x*blockDim.x + threadIdx.x;
    if(i >= BB*CMEML*EE*4) return;
    int b = i >> 19;
    int rem = i & ((1<<19)-1);
    int r = rem >> 11;
    int t2 = rem & 2047;
    int e = t2 >> 2, kk = t2 & 3;
    convA[i] = mem[((long long)b*MEML + r*4 + kk)*EE + e];
}

// ================== tf32 mma GEMM: C[M,N] = A[M,K]@B (+bias) ==================
// BT=0: B is KxN row-major. BT=1: B is NxK row-major (transposed use).
// block tile 128x64, 256 threads (8 warps), warp tile 32x32, BK=16.
template<int BT>
__global__ void __launch_bounds__(256) k_gemm_mma(const float* __restrict__ A,
                                                  const float* __restrict__ Bm,
                                                  const float* __restrict__ bias,
                                                  float* __restrict__ C,
                                                  int M, int N, int K){
    __shared__ float As[128*20];
    __shared__ float Bs[16*68];
    const int tid = threadIdx.x;
    const int w = tid >> 5, lane = tid & 31;
    const int g = lane >> 2, q = lane & 3;
    const int wm = w & 3, wn = w >> 2;
    const int m0 = blockIdx.y * 128;
    const int n0 = blockIdx.x * 64;

    float acc[2][4][4];
    #pragma unroll
    for(int mt=0;mt<2;mt++)
        #pragma unroll
        for(int nt=0;nt<4;nt++)
            #pragma unroll
            for(int e=0;e<4;e++) acc[mt][nt][e] = 0.f;

    const unsigned* Asu = (const unsigned*)As;
    const unsigned* Bsu = (const unsigned*)Bs;

    for(int k0=0; k0<K; k0+=16){
        // load A 128x16
        #pragma unroll
        for(int li=0; li<2; li++){
            int idx = tid + li*256;
            int row = idx >> 2, c4 = (idx & 3)*4;
            float4 v = *(const float4*)(A + (long long)(m0+row)*K + k0 + c4);
            As[row*20 + c4 + 0] = tf32r(v.x);
            As[row*20 + c4 + 1] = tf32r(v.y);
            As[row*20 + c4 + 2] = tf32r(v.z);
            As[row*20 + c4 + 3] = tf32r(v.w);
        }
        // load B 16x64
        if(BT){
            #pragma unroll
            for(int li=0; li<4; li++){
                int idx = tid + li*256;
                int n = idx & 63, kk = idx >> 6;
                Bs[kk*68 + n] = tf32r(Bm[(long long)(n0+n)*K + k0 + kk]);
            }
        } else {
            int row = tid >> 4, c4 = (tid & 15)*4;
            float4 v = *(const float4*)(Bm + (long long)(k0+row)*N + n0 + c4);
            Bs[row*68 + c4 + 0] = tf32r(v.x);
            Bs[row*68 + c4 + 1] = tf32r(v.y);
            Bs[row*68 + c4 + 2] = tf32r(v.z);
            Bs[row*68 + c4 + 3] = tf32r(v.w);
        }
        __syncthreads();
        #pragma unroll
        for(int k8=0; k8<2; k8++){
            int kr = k8*8;
            #pragma unroll
            for(int mt=0; mt<2; mt++){
                unsigned a[4];
                int mb = wm*32 + mt*16;
                a[0] = Asu[(mb+g)*20   + kr+q];
                a[1] = Asu[(mb+g+8)*20 + kr+q];
                a[2] = Asu[(mb+g)*20   + kr+q+4];
                a[3] = Asu[(mb+g+8)*20 + kr+q+4];
                #pragma unroll
                for(int nt=0; nt<4; nt++){
                    unsigned b[2];
                    int nb = wn*32 + nt*8;
                    b[0] = Bsu[(kr+q)*68   + nb+g];
                    b[1] = Bsu[(kr+q+4)*68 + nb+g];
                    mma_tf32(acc[mt][nt], a, b);
                }
            }
        }
        __syncthreads();
    }
    #pragma unroll
    for(int mt=0; mt<2; mt++){
        int r1 = m0 + wm*32 + mt*16 + g;
        #pragma unroll
        for(int nt=0; nt<4; nt++){
            int col = n0 + wn*32 + nt*8 + 2*q;
            float b0 = bias ? bias[col] : 0.f;
            float b1 = bias ? bias[col+1] : 0.f;
            C[(long long)r1*N + col]       = acc[mt][nt][0] + b0;
            C[(long long)r1*N + col+1]     = acc[mt][nt][1] + b1;
            C[(long long)(r1+8)*N + col]   = acc[mt][nt][2] + b0;
            C[(long long)(r1+8)*N + col+1] = acc[mt][nt][3] + b1;
        }
    }
}

// ================== attention (mma tf32 flash, 64 q-tile) ==================
__global__ void __launch_bounds__(256,1) k_attn_mma(const float* __restrict__ pe,
                                                    float* __restrict__ wout,
                                                    const float* __restrict__ gq,
                                                    const float* __restrict__ gkv,
                                                    float* __restrict__ go,
                                                    float* __restrict__ gm,
                                                    float* __restrict__ gl){
    extern __shared__ float smx[];
    float* q_s   = smx;                 // [64][68]
    float* k_s   = q_s + 64*68;         // [j][d]
    float* v_s   = k_s + 64*68;         // [d][j] transposed
    float* pe_s  = v_s + 64*68;         // [128][68]
    float* u_s   = pe_s + 128*68;       // [64][132]
    float* p_s   = u_s + 64*132;        // [64][68]
    float* m_row = p_s + 64*68;
    float* l_row = m_row + 64;
    float* corr_row = l_row + 64;

    const int it = blockIdx.x, h = blockIdx.y, b = blockIdx.z;
    const int i0 = it*64;
    const int t = threadIdx.x;
    const int w = t >> 5, lane = t & 31;
    const int g = lane >> 2, q = lane & 3;
    const int mw = w & 3, half = w >> 2;

    const float* kbase  = gkv + ((long long)b*KVL)*1024 + h*64;
    const float* vbase  = kbase + 512;
    const float* pebase = pe + (long long)h*KVL*64;
    const long long wbase = (((long long)(b*HH + h))*TT + i0)*KVL;

    for(int idx=t; idx<4096; idx+=256){
        int row = idx>>6, col = idx&63;
        q_s[row*68+col] = tf32r(gq[((long long)(b*TT+i0+row))*EE + h*64 + col]);
    }
    if(t < 64){ m_row[t] = -INFINITY; l_row[t] = 0.f; }

    float oacc[4][4];
    #pragma unroll
    for(int nt=0;nt<4;nt++)
        #pragma unroll
        for(int e=0;e<4;e++) oacc[nt][e] = 0.f;

    const unsigned* qsu = (const unsigned*)q_s;
    const unsigned* ksu = (const unsigned*)k_s;
    const unsigned* vsu = (const unsigned*)v_s;
    const unsigned* peu = (const unsigned*)pe_s;
    const unsigned* psu = (const unsigned*)p_s;

    for(int ch=0; ch<KVL/64; ch++){
        const int j0 = ch*64;
        const int rb = 960 + j0 - i0;
        __syncthreads();
        for(int idx=t; idx<4096; idx+=256){
            int row = idx>>6, col = idx&63;
            k_s[row*68+col] = tf32r(kbase[(long long)(j0+row)*1024 + col]);
            v_s[col*68+row] = tf32r(vbase[(long long)(j0+row)*1024 + col]);
        }
        for(int idx=t; idx<8192; idx+=256){
            int row = idx>>6, col = idx&63;
            int r = rb + row;
            pe_s[row*68+col] = (r < KVL) ? tf32r(pebase[(long long)r*64 + col]) : 0.f;
        }
        __syncthreads();

        // U = Q . PE^T (m16 x 64rho x 64k per warp) and S1 = Q . K^T (m16 x 32 per warp)
        float uacc[8][4], sacc[4][4];
        #pragma unroll
        for(int nt=0;nt<8;nt++){ uacc[nt][0]=0.f; uacc[nt][1]=0.f; uacc[nt][2]=0.f; uacc[nt][3]=0.f; }
        #pragma unroll
        for(int nt=0;nt<4;nt++){ sacc[nt][0]=0.f; sacc[nt][1]=0.f; sacc[nt][2]=0.f; sacc[nt][3]=0.f; }
        #pragma unroll
        for(int ks=0; ks<8; ks++){
            int k0 = ks*8;
            unsigned a[4];
            int mb = mw*16;
            a[0] = qsu[(mb+g)*68   + k0+q];
            a[1] = qsu[(mb+g+8)*68 + k0+q];
            a[2] = qsu[(mb+g)*68   + k0+q+4];
            a[3] = qsu[(mb+g+8)*68 + k0+q+4];
            #pragma unroll
            for(int nt=0; nt<8; nt++){
                unsigned bb[2];
                int nb = half*64 + nt*8;
                bb[0] = peu[(nb+g)*68 + k0+q];
                bb[1] = peu[(nb+g)*68 + k0+q+4];
                mma_tf32(uacc[nt], a, bb);
            }
            #pragma unroll
            for(int nt=0; nt<4; nt++){
                unsigned bb[2];
                int nb = half*32 + nt*8;
                bb[0] = ksu[(nb+g)*68 + k0+q];
                bb[1] = ksu[(nb+g)*68 + k0+q+4];
                mma_tf32(sacc[nt], a, bb);
            }
        }
        // write U to smem
        {
            int i1 = mw*16 + g, i2 = i1 + 8;
            #pragma unroll
            for(int nt=0; nt<8; nt++){
                int rho = half*64 + nt*8 + 2*q;
                u_s[i1*132 + rho]   = uacc[nt][0];
                u_s[i1*132 + rho+1] = uacc[nt][1];
                u_s[i2*132 + rho]   = uacc[nt][2];
                u_s[i2*132 + rho+1] = uacc[nt][3];
            }
        }
        __syncthreads();
        // combine raw scores into p_s
        {
            int i1 = mw*16 + g, i2 = i1 + 8;
            #pragma unroll
            for(int nt=0; nt<4; nt++){
                int j_ = half*32 + nt*8 + 2*q;
                p_s[i1*68 + j_]   = SCL*(sacc[nt][0] + u_s[i1*132 + 63 + j_   - i1]);
                p_s[i1*68 + j_+1] = SCL*(sacc[nt][1] + u_s[i1*132 + 63 + j_+1 - i1]);
                p_s[i2*68 + j_]   = SCL*(sacc[nt][2] + u_s[i2*132 + 63 + j_   - i2]);
                p_s[i2*68 + j_+1] = SCL*(sacc[nt][3] + u_s[i2*132 + 63 + j_+1 - i2]);
            }
        }
        __syncthreads();
        // raw score dump to weights output
        for(int idx=t; idx<4096; idx+=256){
            int row = idx>>6, col = idx&63;
            wout[wbase + (long long)row*KVL + j0 + col] = p_s[row*68 + col];
        }
        __syncthreads();
        // online softmax: warp w handles rows 8w..8w+7, 4 lanes per row
        {
            int r = w*8 + (lane>>2);
            int c0 = lane & 3;
            float vals[16];
            float mx = -INFINITY;
            #pragma unroll
            for(int ii=0; ii<16; ii++){
                vals[ii] = p_s[r*68 + c0 + ii*4];
                mx = fmaxf(mx, vals[ii]);
            }
            mx = fmaxf(mx, __shfl_xor_sync(0xffffffffu, mx, 1));
            mx = fmaxf(mx, __shfl_xor_sync(0xffffffffu, mx, 2));
            float mo = m_row[r];
            float mn = fmaxf(mo, mx);
            float corr = __expf(mo - mn);
            float ps = 0.f;
            #pragma unroll
            for(int ii=0; ii<16; ii++){
                float p = tf32r(__expf(vals[ii] - mn));
                p_s[r*68 + c0 + ii*4] = p;
                ps += p;
            }
            ps += __shfl_xor_sync(0xffffffffu, ps, 1);
            ps += __shfl_xor_sync(0xffffffffu, ps, 2);
            if((lane&3)==0){
                l_row[r] = l_row[r]*corr + ps;
                m_row[r] = mn;
                corr_row[r] = corr;
            }
        }
        __syncthreads();
        // AV: scale O by corr, then O += P . V
        {
            float c1 = corr_row[mw*16+g], c2 = corr_row[mw*16+g+8];
            #pragma unroll
            for(int nt=0; nt<4; nt++){
                oacc[nt][0] *= c1; oacc[nt][1] *= c1;
                oacc[nt][2] *= c2; oacc[nt][3] *= c2;
            }
            #pragma unroll
            for(int ks=0; ks<8; ks++){
                int k0 = ks*8;
                unsigned a[4];
                int mb = mw*16;
                a[0] = psu[(mb+g)*68   + k0+q];
                a[1] = psu[(mb+g+8)*68 + k0+q];
                a[2] = psu[(mb+g)*68   + k0+q+4];
                a[3] = psu[(mb+g+8)*68 + k0+q+4];
                #pragma unroll
                for(int nt=0; nt<4; nt++){
                    unsigned bb[2];
                    int db = half*32 + nt*8;
                    bb[0] = vsu[(db+g)*68 + k0+q];
                    bb[1] = vsu[(db+g)*68 + k0+q+4];
                    mma_tf32(oacc[nt], a, bb);
                }
            }
        }
    }
    __syncthreads();
    {
        int i1 = mw*16 + g, i2 = i1 + 8;
        float inv1 = 1.f/l_row[i1], inv2 = 1.f/l_row[i2];
        #pragma unroll
        for(int nt=0; nt<4; nt++){
            int d_ = half*32 + nt*8 + 2*q;
            long long o1 = ((long long)(b*TT + i0 + i1))*EE + h*64 + d_;
            long long o2 = ((long long)(b*TT + i0 + i2))*EE + h*64 + d_;
            go[o1]   = oacc[nt][0]*inv1;
            go[o1+1] = oacc[nt][1]*inv1;
            go[o2]   = oacc[nt][2]*inv2;
            go[o2+1] = oacc[nt][3]*inv2;
        }
    }
    if(t < 64){
        long long gmi = ((long long)(b*HH + h))*TT + i0 + t;
        gm[gmi] = m_row[t];
        gl[gmi] = l_row[t];
    }
}

__global__ void k_rescale(float* __restrict__ w, const float* __restrict__ gm,
                          const float* __restrict__ gl){
    long long row = blockIdx.x;
    float mm = gm[row];
    float invl = 1.f / gl[row];
    float* wr = w + row*KVL;
    for(int j=threadIdx.x; j<KVL; j+=blockDim.x)
        wr[j] = __expf(wr[j] - mm) * invl;
}

// ================== aux loss (two flash passes, mma tf32) ==================
__global__ void __launch_bounds__(256) k_aux_mma(const float* __restrict__ gq,
                                                 const float* __restrict__ gkv,
                                                 const float* __restrict__ gckv,
                                                 float* __restrict__ auxp){
    extern __shared__ float smx[];
    float* q_s   = smx;                 // [64][68]
    float* k_s   = q_s + 64*68;
    float* v_s   = k_s + 64*68;         // [d][j]
    float* p_s   = v_s + 64*68;
    float* o1_s  = p_s + 64*68;         // [64][68]
    float* m_row = o1_s + 64*68;
    float* l_row = m_row + 64;
    float* corr_row = l_row + 64;
    float* red   = corr_row + 64;       // [256]

    const int it = blockIdx.x, h = blockIdx.y, b = blockIdx.z;
    const int i0 = it*64;
    const int t = threadIdx.x;
    const int w = t >> 5, lane = t & 31;
    const int g = lane >> 2, q = lane & 3;
    const int mw = w & 3, half = w >> 2;

    for(int idx=t; idx<4096; idx+=256){
        int row = idx>>6, col = idx&63;
        q_s[row*68+col] = tf32r(gq[((long long)(b*TT+i0+row))*EE + h*64 + col]);
    }

    const unsigned* qsu = (const unsigned*)q_s;
    const unsigned* ksu = (const unsigned*)k_s;
    const unsigned* vsu = (const unsigned*)v_s;
    const unsigned* psu = (const unsigned*)p_s;

    float dsum = 0.f;
    for(int pass=0; pass<2; pass++){
        const int nch = pass ? (CMEML/64) : (MEML/64);
        const float* kb = pass ? (gckv + ((long long)b*CMEML)*1024 + h*64)
                               : (gkv  + ((long long)(b*KVL + CMEML))*1024 + h*64);
        __syncthreads();
        if(t < 64){ m_row[t] = -INFINITY; l_row[t] = 0.f; }
        float oacc[4][4];
        #pragma unroll
        for(int nt=0;nt<4;nt++)
            #pragma unroll
            for(int e=0;e<4;e++) oacc[nt][e] = 0.f;

        for(int ch=0; ch<nch; ch++){
            const int j0 = ch*64;
            __syncthreads();
            for(int idx=t; idx<4096; idx+=256){
                int row = idx>>6, col = idx&63;
                k_s[row*68+col] = tf32r(kb[(long long)(j0+row)*1024 + col]);
                v_s[col*68+row] = tf32r(kb[(long long)(j0+row)*1024 + 512 + col]);
            }
            __syncthreads();
            float sacc[4][4];
            #pragma unroll
            for(int nt=0;nt<4;nt++){ sacc[nt][0]=0.f; sacc[nt][1]=0.f; sacc[nt][2]=0.f; sacc[nt][3]=0.f; }
            #pragma unroll
            for(int ks=0; ks<8; ks++){
                int k0 = ks*8;
                unsigned a[4];
                int mb = mw*16;
                a[0] = qsu[(mb+g)*68   + k0+q];
                a[1] = qsu[(mb+g+8)*68 + k0+q];
                a[2] = qsu[(mb+g)*68   + k0+q+4];
                a[3] = qsu[(mb+g+8)*68 + k0+q+4];
                #pragma unroll
                for(int nt=0; nt<4; nt++){
                    unsigned bb[2];
                    int nb = half*32 + nt*8;
                    bb[0] = ksu[(nb+g)*68 + k0+q];
                    bb[1] = ksu[(nb+g)*68 + k0+q+4];
                    mma_tf32(sacc[nt], a, bb);
                }
            }
            {
                int i1 = mw*16 + g, i2 = i1 + 8;
                #pragma unroll
                for(int nt=0; nt<4; nt++){
                    int j_ = half*32 + nt*8 + 2*q;
                    p_s[i1*68 + j_]   = SCL*sacc[nt][0];
                    p_s[i1*68 + j_+1] = SCL*sacc[nt][1];
                    p_s[i2*68 + j_]   = SCL*sacc[nt][2];
                    p_s[i2*68 + j_+1] = SCL*sacc[nt][3];
                }
            }
            __syncthreads();
            {
                int r = w*8 + (lane>>2);
                int c0 = lane & 3;
                float vals[16];
                float mx = -INFINITY;
                #pragma unroll
                for(int ii=0; ii<16; ii++){
                    vals[ii] = p_s[r*68 + c0 + ii*4];
                    mx = fmaxf(mx, vals[ii]);
                }
                mx = fmaxf(mx, __shfl_xor_sync(0xffffffffu, mx, 1));
                mx = fmaxf(mx, __shfl_xor_sync(0xffffffffu, mx, 2));
                float mo = m_row[r];
                float mn = fmaxf(mo, mx);
                float corr = __expf(mo - mn);
                float ps = 0.f;
                #pragma unroll
                for(int ii=0; ii<16; ii++){
                    float p = tf32r(__expf(vals[ii] - mn));
                    p_s[r*68 + c0 + ii*4] = p;
                    ps += p;
                }
                ps += __shfl_xor_sync(0xffffffffu, ps, 1);
                ps += __shfl_xor_sync(0xffffffffu, ps, 2);
                if((lane&3)==0){
                    l_row[r] = l_row[r]*corr + ps;
                    m_row[r] = mn;
                    corr_row[r] = corr;
                }
            }
            __syncthreads();
            {
                float c1 = corr_row[mw*16+g], c2 = corr_row[mw*16+g+8];
                #pragma unroll
                for(int nt=0; nt<4; nt++){
                    oacc[nt][0] *= c1; oacc[nt][1] *= c1;
                    oacc[nt][2] *= c2; oacc[nt][3] *= c2;
                }
                #pragma unroll
                for(int ks=0; ks<8; ks++){
                    int k0 = ks*8;
                    unsigned a[4];
                    int mb = mw*16;
                    a[0] = psu[(mb+g)*68   + k0+q];
                    a[1] = psu[(mb+g+8)*68 + k0+q];
                    a[2] = psu[(mb+g)*68   + k0+q+4];
                    a[3] = psu[(mb+g+8)*68 + k0+q+4];
                    #pragma unroll
                    for(int nt=0; nt<4; nt++){
                        unsigned bb[2];
                        int db = half*32 + nt*8;
                        bb[0] = vsu[(db+g)*68 + k0+q];
                        bb[1] = vsu[(db+g)*68 + k0+q+4];
                        mma_tf32(oacc[nt], a, bb);
                    }
                }
            }
        }
        __syncthreads();
        {
            int i1 = mw*16 + g, i2 = i1 + 8;
            float inv1 = 1.f/l_row[i1], inv2 = 1.f/l_row[i2];
            if(pass == 0){
                #pragma unroll
                for(int nt=0; nt<4; nt++){
                    int d_ = half*32 + nt*8 + 2*q;
                    o1_s[i1*68 + d_]   = oacc[nt][0]*inv1;
                    o1_s[i1*68 + d_+1] = oacc[nt][1]*inv1;
                    o1_s[i2*68 + d_]   = oacc[nt][2]*inv2;
                    o1_s[i2*68 + d_+1] = oacc[nt][3]*inv2;
                }
            } else {
                #pragma unroll
                for(int nt=0; nt<4; nt++){
                    int d_ = half*32 + nt*8 + 2*q;
                    float d0 = o1_s[i1*68 + d_]   - oacc[nt][0]*inv1;
                    float d1 = o1_s[i1*68 + d_+1] - oacc[nt][1]*inv1;
                    float d2 = o1_s[i2*68 + d_]   - oacc[nt][2]*inv2;
                    float d3 = o1_s[i2*68 + d_+1] - oacc[nt][3]*inv2;
                    dsum += d0*d0 + d1*d1 + d2*d2 + d3*d3;
                }
            }
        }
    }
    red[t] = dsum;
    __syncthreads();
    for(int s2=128; s2>0; s2>>=1){
        if(t < s2) red[t] += red[t + s2];
        __syncthreads();
    }
    if(t == 0)
        auxp[(blockIdx.z*8 + blockIdx.y)*16 + blockIdx.x] = red[0];
}

__global__ void k_auxfin(const float* __restrict__ auxp, float* __restrict__ dst){
    __shared__ float red[512];
    int t = threadIdx.x;
    red[t] = auxp[t];
    __syncthreads();
    for(int s2=256; s2>0; s2>>=1){
        if(t < s2) red[t] += red[t + s2];
        __syncthreads();
    }
    if(t == 0) dst[0] = red[0] / 2097152.0f;
}

extern "C" void kernel_launch(void* const* d_in, const int* in_sizes, int n_in,
                              void* d_out, int out_size) {
    const float* x      = (const float*)d_in[0];
    const float* mem    = (const float*)d_in[1];
    const float* cmem   = (const float*)d_in[2];
    const float* pe     = (const float*)d_in[3];
    const float* Wq     = (const float*)d_in[4];
    const float* Wkv    = (const float*)d_in[5];
    const float* Wout   = (const float*)d_in[6];
    const float* bout   = (const float*)d_in[7];
    const float* conv_w = (const float*)d_in[8];
    const float* conv_b = (const float*)d_in[9];
    float* out = (float*)d_out;

    float* S = 0;
    cudaGetSymbolAddress((void**)&S, g_scratch);
    float* sq    = S + S_Q;
    float* skvin = S + S_KVIN;
    float* skv   = S + S_KV;
    float* scm   = S + S_CM;
    float* sckv  = S + S_CKV;
    float* sconvA= S + S_CONVA;
    float* so    = S + S_O;
    float* sm_   = S + S_M;
    float* sl_   = S + S_L;
    float* sauxp = S + S_AUXP;

    const int ATTN_SMEM = 34752*4;
    const int AUX_SMEM  = 22208*4;
    cudaFuncSetAttribute(k_attn_mma, cudaFuncAttributeMaxDynamicSharedMemorySize, ATTN_SMEM);
    cudaFuncSetAttribute(k_aux_mma,  cudaFuncAttributeMaxDynamicSharedMemorySize, AUX_SMEM);

    // new_mem = x
    cudaMemcpyAsync(out + OFF_NEWMEM, x, (size_t)BB*TT*EE*4, cudaMemcpyDeviceToDevice);

    // kv_input concat + kv GEMM
    k_concat<<<(BB*KVL*EE/4 + 255)/256, 256>>>(x, mem, cmem, skvin);
    k_gemm_mma<0><<<dim3(2*EE/64, BB*KVL/128), 256>>>(skvin, Wkv, (const float*)0, skv, BB*KVL, 2*EE, EE);

    // q GEMM
    k_gemm_mma<0><<<dim3(EE/64, BB*TT/128), 256>>>(x, Wq, (const float*)0, sq, BB*TT, EE, EE);

    // conv (compressed_mem) + new_cmem + ckv GEMM
    k_convA<<<(BB*CMEML*EE*4 + 255)/256, 256>>>(mem, sconvA);
    k_gemm_mma<1><<<dim3(EE/64, BB*CMEML/128), 256>>>(sconvA, conv_w, conv_b, scm, BB*CMEML, EE, EE*4);
    cudaMemcpyAsync(out + OFF_NEWCMEM, scm, (size_t)BB*CMEML*EE*4, cudaMemcpyDeviceToDevice);
    k_gemm_mma<0><<<dim3(2*EE/64, BB*CMEML/128), 256>>>(scm, Wkv, (const float*)0, sckv, BB*CMEML, 2*EE, EE);

    // attention
    k_attn_mma<<<dim3(TT/64, HH, BB), 256, ATTN_SMEM>>>(pe, out + OFF_W, sq, skv, so, sm_, sl_);
    k_rescale<<<BB*HH*TT, 256>>>(out + OFF_W, sm_, sl_);

    // logits
    k_gemm_mma<0><<<dim3(EE/64, BB*TT/128), 256>>>(so, Wout, bout, out + OFF_LOGITS, BB*TT, EE, EE);

    // aux loss
    k_aux_mma<<<dim3(TT/64, HH, BB), 256, AUX_SMEM>>>(sq, skv, sckv, sauxp);
    k_auxfin<<<1, 512>>>(sauxp, out + OFF_AUX);
}